// round 12
// baseline (speedup 1.0000x reference)
#include <cuda_runtime.h>
#include <cuda_fp16.h>
#include <cstdint>
#include <cstddef>

// ---------------------------------------------------------------------------
// Problem constants
// ---------------------------------------------------------------------------
#define BTOT   4096
#define NTOK   49
#define CDIM   384
#define HEADS  12
#define HDIM   32
#define MROWS  (BTOT * NTOK)        // 200704
#define KDIM   384
#define N_QKV  1152

// Scratch (__device__ globals: the allowed alloc-free pattern)
__device__ __half g_qkvh[(size_t)MROWS * N_QKV];  // 462 MB
__device__ __half g_ctxh[(size_t)MROWS * CDIM];   // 154 MB
__device__ __half g_wqh [(size_t)N_QKV * KDIM];   // W_qkv^T as half [N][K]
__device__ __half g_wph [(size_t)CDIM * KDIM];    // W_proj^T as half [N][K]
__device__ float  g_bias[(size_t)HEADS * NTOK * NTOK];

// ---------------------------------------------------------------------------
// Helpers
// ---------------------------------------------------------------------------
__device__ __forceinline__ uint32_t smem_u32(const void* p) {
    return (uint32_t)__cvta_generic_to_shared(p);
}
__device__ __forceinline__ void cp16(uint32_t dst, const void* src) {
    asm volatile("cp.async.cg.shared.global [%0], [%1], 16;" :: "r"(dst), "l"(src));
}
__device__ __forceinline__ void cp_commit() {
    asm volatile("cp.async.commit_group;" ::: "memory");
}
__device__ __forceinline__ void cp_wait1() {
    asm volatile("cp.async.wait_group 1;" ::: "memory");
}
__device__ __forceinline__ void cp_wait0() {
    asm volatile("cp.async.wait_group 0;" ::: "memory");
}

__device__ __forceinline__ void ldsm4(uint32_t& r0, uint32_t& r1, uint32_t& r2,
                                      uint32_t& r3, uint32_t a) {
    asm volatile("ldmatrix.sync.aligned.m8n8.x4.shared.b16 {%0,%1,%2,%3}, [%4];"
                 : "=r"(r0), "=r"(r1), "=r"(r2), "=r"(r3) : "r"(a));
}
__device__ __forceinline__ void ldsm4t(uint32_t& r0, uint32_t& r1, uint32_t& r2,
                                       uint32_t& r3, uint32_t a) {
    asm volatile("ldmatrix.sync.aligned.m8n8.x4.trans.shared.b16 {%0,%1,%2,%3}, [%4];"
                 : "=r"(r0), "=r"(r1), "=r"(r2), "=r"(r3) : "r"(a));
}

__device__ __forceinline__ void mma_f16(float c[4], const uint32_t a[4],
                                        const uint32_t b[2]) {
    asm volatile(
        "mma.sync.aligned.m16n8k16.row.col.f32.f16.f16.f32 "
        "{%0,%1,%2,%3}, {%4,%5,%6,%7}, {%8,%9}, {%0,%1,%2,%3};"
        : "+f"(c[0]), "+f"(c[1]), "+f"(c[2]), "+f"(c[3])
        : "r"(a[0]), "r"(a[1]), "r"(a[2]), "r"(a[3]), "r"(b[0]), "r"(b[1]));
}

__device__ __forceinline__ uint32_t packh2(float lo, float hi) {
    __half2 h = __floats2half2_rn(lo, hi);
    return *(uint32_t*)&h;
}

// ---------------------------------------------------------------------------
// Prep kernels
// ---------------------------------------------------------------------------
// Wt[n][k] = (half)W[k][n];  W is K x N row-major, K,N multiples of 32
__global__ void transpose_h_kernel(const float* __restrict__ W,
                                   __half* __restrict__ Wt, int K, int N)
{
    __shared__ float t[32][33];
    int kb = blockIdx.y * 32, nb = blockIdx.x * 32;
    int x = threadIdx.x, y = threadIdx.y;
    #pragma unroll
    for (int i = y; i < 32; i += 8)
        t[i][x] = W[(size_t)(kb + i) * N + nb + x];
    __syncthreads();
    #pragma unroll
    for (int i = y; i < 32; i += 8)
        Wt[(size_t)(nb + i) * K + kb + x] = __float2half_rn(t[x][i]);
}

__global__ void bias_build_kernel(const float* __restrict__ table,
                                  const int* __restrict__ relix,
                                  float* __restrict__ bias_g)
{
    int idx = blockIdx.x * blockDim.x + threadIdx.x;
    if (idx < HEADS * NTOK * NTOK) {
        int h = idx / (NTOK * NTOK), ij = idx % (NTOK * NTOK);
        bias_g[idx] = table[relix[ij] * HEADS + h];
    }
}

// ---------------------------------------------------------------------------
// GEMM1 variant: qkv = half( x_f32 @ Wt^T + bias )
// A arrives as f32 via cp.async into an f32 stage; a smem->smem convert pass
// (LDS.128 -> cvt -> STS.128, conflict-free both ways) produces the half A
// tile right before compute. Fragment/compute path is the validated round-8
// BK=32 / stride-80 / 64x64-warp-tile configuration, 128 threads, 4 warps.
// smem: f32A 2x18.4K + halfA 10.2K + B 2x10.2K = 66K -> 3 CTAs/SM.
// ---------------------------------------------------------------------------
#define F32A_STR   144                    // f32 stage row stride bytes (128 data)
#define F32A_TILE  (128 * F32A_STR)       // 18432
#define HB_STR     80                     // half row stride bytes (64 data)
#define HB_TILE    (128 * HB_STR)         // 10240
// layout: [f32A s0][f32A s1][halfA][B s0][B s1]
#define QK_OFF_HA  (2 * F32A_TILE)                // 36864
#define QK_OFF_B0  (QK_OFF_HA + HB_TILE)          // 47104
#define QK_SMEM    (QK_OFF_B0 + 2 * HB_TILE)      // 67584

__global__ void __launch_bounds__(128, 3)
gemm_qkv_kernel(const float* __restrict__ A, const __half* __restrict__ Bt,
                const float* __restrict__ bias, __half* __restrict__ C,
                int Ncols)
{
    extern __shared__ char smem[];
    const uint32_t sb = smem_u32(smem);

    const int tid  = threadIdx.x;
    const int warp = tid >> 5, lane = tid & 31;
    const int wm   = warp >> 1, wn = warp & 1;     // 2 x 2 warp grid
    const int g    = lane >> 2, t = lane & 3;
    const int m0   = blockIdx.y * 128;
    const int n0   = blockIdx.x * 128;

    float acc[4][8][4];
    #pragma unroll
    for (int mi = 0; mi < 4; mi++)
        #pragma unroll
        for (int nj = 0; nj < 8; nj++)
            #pragma unroll
            for (int r = 0; r < 4; r++) acc[mi][nj][r] = 0.f;

    const char* gA = (const char*)(A + (size_t)m0 * KDIM);   // f32 rows, 1536 B
    const char* gB = (const char*)Bt + (size_t)n0 * 768;     // half rows, 768 B

    // stage loader for k-tile kt into buffer s (f32 A + half B)
    auto load_stage = [&](int kt, int s) {
        const uint32_t aBase = sb + s * F32A_TILE;
        const uint32_t bBase = sb + QK_OFF_B0 + s * HB_TILE;
        #pragma unroll
        for (int j = 0; j < 8; j++) {              // A: 128 rows x 8 chunks 16B
            int c = tid + j * 128;
            int row = c >> 3, ch = c & 7;
            cp16(aBase + row * F32A_STR + ch * 16,
                 gA + (size_t)row * 1536 + kt * 128 + ch * 16);
        }
        #pragma unroll
        for (int j = 0; j < 4; j++) {              // B: 128 rows x 4 chunks 16B
            int c = tid + j * 128;
            int row = c >> 2, ch = c & 3;
            cp16(bBase + row * HB_STR + ch * 16,
                 gB + (size_t)row * 768 + kt * 64 + ch * 16);
        }
    };

    // f32 stage s -> halfA (one row of 32 floats per thread)
    auto convert = [&](int s) {
        const float* src = (const float*)(smem + s * F32A_TILE + tid * F32A_STR);
        uint32_t dst = sb + QK_OFF_HA + tid * HB_STR;
        float4 v[8];
        #pragma unroll
        for (int i = 0; i < 8; i++) v[i] = *(const float4*)(src + i * 4);
        #pragma unroll
        for (int i = 0; i < 4; i++) {
            uint4 p = make_uint4(packh2(v[2*i].x,   v[2*i].y),
                                 packh2(v[2*i].z,   v[2*i].w),
                                 packh2(v[2*i+1].x, v[2*i+1].y),
                                 packh2(v[2*i+1].z, v[2*i+1].w));
            asm volatile("st.shared.v4.b32 [%0], {%1,%2,%3,%4};"
                         :: "r"(dst + i * 16), "r"(p.x), "r"(p.y),
                            "r"(p.z), "r"(p.w) : "memory");
        }
    };

    auto compute = [&](int s) {
        const uint32_t aB = sb + QK_OFF_HA;
        const uint32_t bB = sb + QK_OFF_B0 + s * HB_TILE;
        #pragma unroll
        for (int ks = 0; ks < 2; ks++) {           // 2 k-steps of 16 halfs
            uint32_t af[4][4], bf[8][2];
            #pragma unroll
            for (int mi = 0; mi < 4; mi++) {
                int mb = wm * 64 + mi * 16;
                uint32_t addr = aB + (mb + (lane & 15)) * HB_STR + ks * 32
                              + (lane >> 4) * 16;
                ldsm4(af[mi][0], af[mi][1], af[mi][2], af[mi][3], addr);
            }
            #pragma unroll
            for (int p = 0; p < 4; p++) {
                int j0 = wn * 64 + p * 16;
                uint32_t addr = bB + (j0 + (lane & 7) + ((lane >> 4) << 3)) * HB_STR
                              + ks * 32 + ((lane >> 3) & 1) * 16;
                ldsm4(bf[2 * p][0], bf[2 * p][1], bf[2 * p + 1][0],
                      bf[2 * p + 1][1], addr);
            }
            #pragma unroll
            for (int mi = 0; mi < 4; mi++)
                #pragma unroll
                for (int nj = 0; nj < 8; nj++)
                    mma_f16(acc[mi][nj], af[mi], bf[nj]);
        }
    };

    load_stage(0, 0); cp_commit();

    // per iter: wait(s) -> sync(compute of s^1 retired)
    //          -> issue loads kt+1 into s^1 -> convert(s) -> sync -> compute(s)
    #pragma unroll 1
    for (int kt = 0; kt < 12; kt++) {
        int s = kt & 1;
        cp_wait0();
        __syncthreads();
        if (kt + 1 < 12) { load_stage(kt + 1, s ^ 1); cp_commit(); }
        convert(s);
        __syncthreads();
        compute(s);
    }

    // epilogue (half output)
    #pragma unroll
    for (int mi = 0; mi < 4; mi++) {
        #pragma unroll
        for (int nj = 0; nj < 8; nj++) {
            int row = m0 + wm * 64 + mi * 16 + g;
            int col = n0 + wn * 64 + nj * 8 + 2 * t;
            float2 bb = *(const float2*)(bias + col);
            *(uint32_t*)(C + (size_t)row * Ncols + col)
                = packh2(acc[mi][nj][0] + bb.x, acc[mi][nj][1] + bb.y);
            *(uint32_t*)(C + (size_t)(row + 8) * Ncols + col)
                = packh2(acc[mi][nj][2] + bb.x, acc[mi][nj][3] + bb.y);
        }
    }
}

// ---------------------------------------------------------------------------
// fp16 GEMM (validated round-9 config): C = A_half @ Bt^T + bias
// CTA 128x128, 256 thr = 8 warps (4m x 2n), warp tile 32x64, BK=64.
// ---------------------------------------------------------------------------
#define GSTRB  144                    // smem row stride bytes (72 halfs)
#define TILE_B (128 * GSTRB)          // 18432 per operand tile
#define STG_B  (2 * TILE_B)           // 36864
#define GEMM_SMEM (2 * STG_B)         // 73728

__global__ void __launch_bounds__(256, 2)
gemm_f16_kernel(const __half* __restrict__ A, const __half* __restrict__ Bt,
                const float* __restrict__ bias, void* __restrict__ C,
                int Ncols, int half_out)
{
    extern __shared__ char smem[];
    const uint32_t sb = smem_u32(smem);

    const int tid  = threadIdx.x;
    const int warp = tid >> 5, lane = tid & 31;
    const int wm   = warp >> 1, wn = warp & 1;     // 4 x 2 warp grid
    const int g    = lane >> 2, t = lane & 3;
    const int m0   = blockIdx.y * 128;
    const int n0   = blockIdx.x * 128;

    float acc[2][8][4];
    #pragma unroll
    for (int mi = 0; mi < 2; mi++)
        #pragma unroll
        for (int nj = 0; nj < 8; nj++)
            #pragma unroll
            for (int r = 0; r < 4; r++) acc[mi][nj][r] = 0.f;

    const char* gA = (const char*)A + (size_t)m0 * 768;   // 384 halfs/row
    const char* gB = (const char*)Bt + (size_t)n0 * 768;

    auto load_stage = [&](int kt, int s) {
        const uint32_t base = sb + s * STG_B;
        #pragma unroll
        for (int j = 0; j < 4; j++) {
            int c = tid + j * 256;
            int row = c >> 3, ch = c & 7;
            cp16(base + row * GSTRB + ch * 16,
                 gA + (size_t)row * 768 + kt * 128 + ch * 16);
        }
        #pragma unroll
        for (int j = 0; j < 4; j++) {
            int c = tid + j * 256;
            int row = c >> 3, ch = c & 7;
            cp16(base + TILE_B + row * GSTRB + ch * 16,
                 gB + (size_t)row * 768 + kt * 128 + ch * 16);
        }
    };

    auto compute = [&](int s) {
        const uint32_t aB = sb + s * STG_B;
        const uint32_t bB = aB + TILE_B;
        #pragma unroll
        for (int ks = 0; ks < 4; ks++) {
            uint32_t af[2][4], bf[8][2];
            #pragma unroll
            for (int mi = 0; mi < 2; mi++) {
                int mb = wm * 32 + mi * 16;
                uint32_t addr = aB + (mb + (lane & 15)) * GSTRB + ks * 32
                              + (lane >> 4) * 16;
                ldsm4(af[mi][0], af[mi][1], af[mi][2], af[mi][3], addr);
            }
            #pragma unroll
            for (int p = 0; p < 4; p++) {
                int j0 = wn * 64 + p * 16;
                uint32_t addr = bB + (j0 + (lane & 7) + ((lane >> 4) << 3)) * GSTRB
                              + ks * 32 + ((lane >> 3) & 1) * 16;
                ldsm4(bf[2 * p][0], bf[2 * p][1], bf[2 * p + 1][0],
                      bf[2 * p + 1][1], addr);
            }
            #pragma unroll
            for (int mi = 0; mi < 2; mi++)
                #pragma unroll
                for (int nj = 0; nj < 8; nj++)
                    mma_f16(acc[mi][nj], af[mi], bf[nj]);
        }
    };

    load_stage(0, 0); cp_commit();

    int s = 0;
    #pragma unroll 1
    for (int kt = 0; kt < 6; kt++) {
        if (kt + 1 < 6) { load_stage(kt + 1, s ^ 1); cp_commit(); }
        if (kt + 1 < 6) cp_wait1(); else cp_wait0();
        __syncthreads();
        compute(s);
        __syncthreads();
        s ^= 1;
    }

    #pragma unroll
    for (int mi = 0; mi < 2; mi++) {
        #pragma unroll
        for (int nj = 0; nj < 8; nj++) {
            int row = m0 + wm * 32 + mi * 16 + g;
            int col = n0 + wn * 64 + nj * 8 + 2 * t;
            float2 bb = *(const float2*)(bias + col);
            float a0 = acc[mi][nj][0] + bb.x, a1 = acc[mi][nj][1] + bb.y;
            float a2 = acc[mi][nj][2] + bb.x, a3 = acc[mi][nj][3] + bb.y;
            if (half_out) {
                __half* Ch = (__half*)C;
                *(uint32_t*)(Ch + (size_t)row * Ncols + col)       = packh2(a0, a1);
                *(uint32_t*)(Ch + (size_t)(row + 8) * Ncols + col) = packh2(a2, a3);
            } else {
                float* Cf = (float*)C;
                *(float2*)(Cf + (size_t)row * Ncols + col)       = make_float2(a0, a1);
                *(float2*)(Cf + (size_t)(row + 8) * Ncols + col) = make_float2(a2, a3);
            }
        }
    }
}

// ---------------------------------------------------------------------------
// fp16 tensor-core attention (validated; unchanged).
// Block = (window, head-pair): 128 thr, 4 warps.
// ---------------------------------------------------------------------------
#define HST 40
__global__ void __launch_bounds__(128, 4)
attn_h_kernel(const __half* __restrict__ qkvh, const float* __restrict__ bias_g,
              __half* __restrict__ ctxh)
{
    __shared__ __align__(16) __half q_s[2][64 * HST];
    __shared__ __align__(16) __half k_s[2][64 * HST];
    __shared__ __align__(16) __half v_s[2][64 * HST];

    const int w  = blockIdx.x;
    const int hp = blockIdx.y;
    const int tid = threadIdx.x, wid = tid >> 5, lane = tid & 31;
    const int hh = wid >> 1, mwarp = wid & 1;
    const int h  = hp * 2 + hh;
    const int g  = lane >> 2, t = lane & 3;
    const float scale = 0.1767766952966369f;   // 32^-0.5

    #pragma unroll
    for (int hl = 0; hl < 2; hl++) {
        uint4 z = make_uint4(0u, 0u, 0u, 0u);
        for (int i = tid; i < 75; i += 128) {
            ((uint4*)(q_s[hl] + 49 * HST))[i] = z;
            ((uint4*)(k_s[hl] + 49 * HST))[i] = z;
            ((uint4*)(v_s[hl] + 49 * HST))[i] = z;
        }
    }

    #pragma unroll
    for (int hl = 0; hl < 2; hl++) {
        const char* base = (const char*)(qkvh + (size_t)w * NTOK * N_QKV
                                         + (size_t)(hp * 2 + hl) * HDIM);
        uint32_t sq = smem_u32(q_s[hl]), sk = smem_u32(k_s[hl]), sv = smem_u32(v_s[hl]);
        for (int idx = tid; idx < 588; idx += 128) {
            int mat = idx / 196, rem = idx - mat * 196;
            int r = rem >> 2, ch = rem & 3;
            uint32_t dst = (mat == 0 ? sq : mat == 1 ? sk : sv) + r * 80 + ch * 16;
            cp16(dst, base + (size_t)r * 2304 + mat * 768 + ch * 16);
        }
    }
    cp_commit();
    cp_wait0();
    __syncthreads();

    const uint32_t Q = smem_u32(q_s[hh]);
    const uint32_t K = smem_u32(k_s[hh]);
    const uint32_t V = smem_u32(v_s[hh]);

    float sacc[2][8][4];
    #pragma unroll
    for (int mi = 0; mi < 2; mi++)
        #pragma unroll
        for (int nj = 0; nj < 8; nj++)
            #pragma unroll
            for (int r = 0; r < 4; r++) sacc[mi][nj][r] = 0.f;

    #pragma unroll
    for (int ks = 0; ks < 2; ks++) {
        uint32_t af[2][4], bf[8][2];
        #pragma unroll
        for (int mi = 0; mi < 2; mi++) {
            int mb = mwarp * 32 + mi * 16;
            uint32_t addr = Q + (mb + (lane & 15)) * 80 + ks * 32 + (lane >> 4) * 16;
            ldsm4(af[mi][0], af[mi][1], af[mi][2], af[mi][3], addr);
        }
        #pragma unroll
        for (int p = 0; p < 4; p++) {
            uint32_t addr = K + (p * 16 + (lane & 7) + ((lane >> 4) << 3)) * 80
                          + ks * 32 + ((lane >> 3) & 1) * 16;
            ldsm4(bf[2 * p][0], bf[2 * p][1], bf[2 * p + 1][0], bf[2 * p + 1][1], addr);
        }
        #pragma unroll
        for (int mi = 0; mi < 2; mi++)
            #pragma unroll
            for (int nj = 0; nj < 8; nj++)
                mma_f16(sacc[mi][nj], af[mi], bf[nj]);
    }

    const float* bh = bias_g + (size_t)h * (NTOK * NTOK);
    #pragma unroll
    for (int mi = 0; mi < 2; mi++) {
        int r0 = mwarp * 32 + mi * 16 + g;
        int r1 = r0 + 8;
        int br0 = min(r0, NTOK - 1) * NTOK;
        int br1 = min(r1, NTOK - 1) * NTOK;
        #pragma unroll
        for (int nj = 0; nj < 8; nj++) {
            int c0 = nj * 8 + 2 * t, c1 = c0 + 1;
            sacc[mi][nj][0] = (c0 < NTOK) ? sacc[mi][nj][0] * scale + bh[br0 + c0] : -1e30f;
            sacc[mi][nj][1] = (c1 < NTOK) ? sacc[mi][nj][1] * scale + bh[br0 + c1] : -1e30f;
            sacc[mi][nj][2] = (c0 < NTOK) ? sacc[mi][nj][2] * scale + bh[br1 + c0] : -1e30f;
            sacc[mi][nj][3] = (c1 < NTOK) ? sacc[mi][nj][3] * scale + bh[br1 + c1] : -1e30f;
        }
    }

    #pragma unroll
    for (int mi = 0; mi < 2; mi++) {
        float m0 = -1e30f, m1 = -1e30f;
        #pragma unroll
        for (int nj = 0; nj < 8; nj++) {
            m0 = fmaxf(m0, fmaxf(sacc[mi][nj][0], sacc[mi][nj][1]));
            m1 = fmaxf(m1, fmaxf(sacc[mi][nj][2], sacc[mi][nj][3]));
        }
        m0 = fmaxf(m0, __shfl_xor_sync(0xffffffffu, m0, 1));
        m0 = fmaxf(m0, __shfl_xor_sync(0xffffffffu, m0, 2));
        m1 = fmaxf(m1, __shfl_xor_sync(0xffffffffu, m1, 1));
        m1 = fmaxf(m1, __shfl_xor_sync(0xffffffffu, m1, 2));
        float s0 = 0.f, s1 = 0.f;
        #pragma unroll
        for (int nj = 0; nj < 8; nj++) {
            sacc[mi][nj][0] = __expf(sacc[mi][nj][0] - m0); s0 += sacc[mi][nj][0];
            sacc[mi][nj][1] = __expf(sacc[mi][nj][1] - m0); s0 += sacc[mi][nj][1];
            sacc[mi][nj][2] = __expf(sacc[mi][nj][2] - m1); s1 += sacc[mi][nj][2];
            sacc[mi][nj][3] = __expf(sacc[mi][nj][3] - m1); s1 += sacc[mi][nj][3];
        }
        s0 += __shfl_xor_sync(0xffffffffu, s0, 1);
        s0 += __shfl_xor_sync(0xffffffffu, s0, 2);
        s1 += __shfl_xor_sync(0xffffffffu, s1, 1);
        s1 += __shfl_xor_sync(0xffffffffu, s1, 2);
        float i0 = 1.f / s0, i1 = 1.f / s1;
        #pragma unroll
        for (int nj = 0; nj < 8; nj++) {
            sacc[mi][nj][0] *= i0; sacc[mi][nj][1] *= i0;
            sacc[mi][nj][2] *= i1; sacc[mi][nj][3] *= i1;
        }
    }

    float oacc[2][4][4];
    #pragma unroll
    for (int mi = 0; mi < 2; mi++)
        #pragma unroll
        for (int nd = 0; nd < 4; nd++)
            #pragma unroll
            for (int r = 0; r < 4; r++) oacc[mi][nd][r] = 0.f;

    #pragma unroll
    for (int jt = 0; jt < 4; jt++) {
        uint32_t bf[4][2];
        #pragma unroll
        for (int p = 0; p < 2; p++) {
            uint32_t addr = V + (jt * 16 + (lane & 7) + (((lane >> 3) & 1) << 3)) * 80
                          + p * 32 + ((lane >> 4) << 4);
            ldsm4t(bf[2 * p][0], bf[2 * p][1], bf[2 * p + 1][0], bf[2 * p + 1][1], addr);
        }
        uint32_t pa[2][4];
        #pragma unroll
        for (int mi = 0; mi < 2; mi++) {
            pa[mi][0] = packh2(sacc[mi][2 * jt][0],     sacc[mi][2 * jt][1]);
            pa[mi][1] = packh2(sacc[mi][2 * jt][2],     sacc[mi][2 * jt][3]);
            pa[mi][2] = packh2(sacc[mi][2 * jt + 1][0], sacc[mi][2 * jt + 1][1]);
            pa[mi][3] = packh2(sacc[mi][2 * jt + 1][2], sacc[mi][2 * jt + 1][3]);
        }
        #pragma unroll
        for (int mi = 0; mi < 2; mi++)
            #pragma unroll
            for (int nd = 0; nd < 4; nd++)
                mma_f16(oacc[mi][nd], pa[mi], bf[nd]);
    }

    #pragma unroll
    for (int mi = 0; mi < 2; mi++) {
        int r0 = mwarp * 32 + mi * 16 + g;
        int r1 = r0 + 8;
        #pragma unroll
        for (int nd = 0; nd < 4; nd++) {
            int d0 = nd * 8 + 2 * t;
            if (r0 < NTOK)
                *(uint32_t*)(ctxh + ((size_t)w * NTOK + r0) * CDIM + h * HDIM + d0)
                    = packh2(oacc[mi][nd][0], oacc[mi][nd][1]);
            if (r1 < NTOK)
                *(uint32_t*)(ctxh + ((size_t)w * NTOK + r1) * CDIM + h * HDIM + d0)
                    = packh2(oacc[mi][nd][2], oacc[mi][nd][3]);
        }
    }
}

// ---------------------------------------------------------------------------
// Launch
// ---------------------------------------------------------------------------
extern "C" void kernel_launch(void* const* d_in, const int* in_sizes, int n_in,
                              void* d_out, int out_size)
{
    const float* x     = (const float*)d_in[0];
    const float* Wqkv  = (const float*)d_in[1];
    const float* bqkv  = (const float*)d_in[2];
    const float* Wproj = (const float*)d_in[3];
    const float* bproj = (const float*)d_in[4];
    const float* table = (const float*)d_in[5];
    const int*   relix = (const int*)d_in[6];
    float* out = (float*)d_out;

    __half *qkvh, *ctxh, *wqh, *wph;
    float* bias_g;
    cudaGetSymbolAddress((void**)&qkvh, g_qkvh);
    cudaGetSymbolAddress((void**)&ctxh, g_ctxh);
    cudaGetSymbolAddress((void**)&wqh,  g_wqh);
    cudaGetSymbolAddress((void**)&wph,  g_wph);
    cudaGetSymbolAddress((void**)&bias_g, g_bias);

    cudaFuncSetAttribute(gemm_f16_kernel,
                         cudaFuncAttributeMaxDynamicSharedMemorySize, GEMM_SMEM);
    cudaFuncSetAttribute(gemm_qkv_kernel,
                         cudaFuncAttributeMaxDynamicSharedMemorySize, QK_SMEM);

    // 0) prep (f2h pass eliminated; conversion lives inside gemm_qkv_kernel)
    transpose_h_kernel<<<dim3(N_QKV / 32, KDIM / 32), dim3(32, 8)>>>(
        Wqkv, wqh, KDIM, N_QKV);
    transpose_h_kernel<<<dim3(CDIM / 32, KDIM / 32), dim3(32, 8)>>>(
        Wproj, wph, KDIM, CDIM);
    bias_build_kernel<<<(HEADS * NTOK * NTOK + 255) / 256, 256>>>(
        table, relix, bias_g);

    // 1) qkv = half(x_f32 @ W_qkv + b)   (M=200704, N=1152, K=384)
    gemm_qkv_kernel<<<dim3(N_QKV / 128, MROWS / 128), 128, QK_SMEM>>>(
        x, wqh, bqkv, qkvh, N_QKV);

    // 2) attention (fp16 tensor-core), one block per (window, head-pair)
    attn_h_kernel<<<dim3(BTOT, HEADS / 2), 128>>>(qkvh, bias_g, ctxh);

    // 3) out = ctx @ W_proj + b          (M=200704, N=384, K=384), f32 out
    gemm_f16_kernel<<<dim3(CDIM / 128, MROWS / 128), 256, GEMM_SMEM>>>(
        ctxh, wph, bproj, out, CDIM, 0);
}

// round 13
// speedup vs baseline: 1.0445x; 1.0445x over previous
#include <cuda_runtime.h>
#include <cuda_fp16.h>
#include <cstdint>
#include <cstddef>

// ---------------------------------------------------------------------------
// Problem constants
// ---------------------------------------------------------------------------
#define BTOT   4096
#define NTOK   49
#define CDIM   384
#define HEADS  12
#define HDIM   32
#define MROWS  (BTOT * NTOK)        // 200704
#define KDIM   384
#define N_QKV  1152

// Scratch (__device__ globals: the allowed alloc-free pattern)
__device__ __half g_qkvh[(size_t)MROWS * N_QKV];  // 462 MB
__device__ __half g_ctxh[(size_t)MROWS * CDIM];   // 154 MB
__device__ __half g_xh  [(size_t)MROWS * KDIM];   // 154 MB
__device__ __half g_wqh [(size_t)N_QKV * KDIM];   // W_qkv^T as half [N][K]
__device__ __half g_wph [(size_t)CDIM * KDIM];    // W_proj^T as half [N][K]
__device__ float  g_bias[(size_t)HEADS * NTOK * NTOK];

// ---------------------------------------------------------------------------
// Helpers
// ---------------------------------------------------------------------------
__device__ __forceinline__ uint32_t smem_u32(const void* p) {
    return (uint32_t)__cvta_generic_to_shared(p);
}
__device__ __forceinline__ void cp16(uint32_t dst, const void* src) {
    asm volatile("cp.async.cg.shared.global [%0], [%1], 16;" :: "r"(dst), "l"(src));
}
__device__ __forceinline__ void cp_commit() {
    asm volatile("cp.async.commit_group;" ::: "memory");
}
__device__ __forceinline__ void cp_wait1() {
    asm volatile("cp.async.wait_group 1;" ::: "memory");
}
__device__ __forceinline__ void cp_wait0() {
    asm volatile("cp.async.wait_group 0;" ::: "memory");
}

__device__ __forceinline__ void ldsm4(uint32_t& r0, uint32_t& r1, uint32_t& r2,
                                      uint32_t& r3, uint32_t a) {
    asm volatile("ldmatrix.sync.aligned.m8n8.x4.shared.b16 {%0,%1,%2,%3}, [%4];"
                 : "=r"(r0), "=r"(r1), "=r"(r2), "=r"(r3) : "r"(a));
}
__device__ __forceinline__ void ldsm4t(uint32_t& r0, uint32_t& r1, uint32_t& r2,
                                       uint32_t& r3, uint32_t a) {
    asm volatile("ldmatrix.sync.aligned.m8n8.x4.trans.shared.b16 {%0,%1,%2,%3}, [%4];"
                 : "=r"(r0), "=r"(r1), "=r"(r2), "=r"(r3) : "r"(a));
}

__device__ __forceinline__ void mma_f16(float c[4], const uint32_t a[4],
                                        const uint32_t b[2]) {
    asm volatile(
        "mma.sync.aligned.m16n8k16.row.col.f32.f16.f16.f32 "
        "{%0,%1,%2,%3}, {%4,%5,%6,%7}, {%8,%9}, {%0,%1,%2,%3};"
        : "+f"(c[0]), "+f"(c[1]), "+f"(c[2]), "+f"(c[3])
        : "r"(a[0]), "r"(a[1]), "r"(a[2]), "r"(a[3]), "r"(b[0]), "r"(b[1]));
}

__device__ __forceinline__ uint32_t packh2(float lo, float hi) {
    __half2 h = __floats2half2_rn(lo, hi);
    return *(uint32_t*)&h;
}

// ---------------------------------------------------------------------------
// Prep kernels
// ---------------------------------------------------------------------------
__global__ void f2h_kernel(const float4* __restrict__ in, uint2* __restrict__ out,
                           int n4)
{
    for (int i = blockIdx.x * blockDim.x + threadIdx.x; i < n4;
         i += gridDim.x * blockDim.x) {
        float4 v = in[i];
        out[i] = make_uint2(packh2(v.x, v.y), packh2(v.z, v.w));
    }
}

// Wt[n][k] = (half)W[k][n];  W is K x N row-major, K,N multiples of 32
__global__ void transpose_h_kernel(const float* __restrict__ W,
                                   __half* __restrict__ Wt, int K, int N)
{
    __shared__ float t[32][33];
    int kb = blockIdx.y * 32, nb = blockIdx.x * 32;
    int x = threadIdx.x, y = threadIdx.y;
    #pragma unroll
    for (int i = y; i < 32; i += 8)
        t[i][x] = W[(size_t)(kb + i) * N + nb + x];
    __syncthreads();
    #pragma unroll
    for (int i = y; i < 32; i += 8)
        Wt[(size_t)(nb + i) * K + kb + x] = __float2half_rn(t[x][i]);
}

__global__ void bias_build_kernel(const float* __restrict__ table,
                                  const int* __restrict__ relix,
                                  float* __restrict__ bias_g)
{
    int idx = blockIdx.x * blockDim.x + threadIdx.x;
    if (idx < HEADS * NTOK * NTOK) {
        int h = idx / (NTOK * NTOK), ij = idx % (NTOK * NTOK);
        bias_g[idx] = table[relix[ij] * HEADS + h];
    }
}

// ---------------------------------------------------------------------------
// fp16 GEMM (validated round-9 config): C = A_half @ Bt^T + bias
// CTA 128x128, 256 thr = 8 warps (4m x 2n), warp tile 32x64, BK=64.
// ---------------------------------------------------------------------------
#define GSTRB  144                    // smem row stride bytes (72 halfs)
#define TILE_B (128 * GSTRB)          // 18432 per operand tile
#define STG_B  (2 * TILE_B)           // 36864
#define GEMM_SMEM (2 * STG_B)         // 73728

__global__ void __launch_bounds__(256, 2)
gemm_f16_kernel(const __half* __restrict__ A, const __half* __restrict__ Bt,
                const float* __restrict__ bias, void* __restrict__ C,
                int Ncols, int half_out)
{
    extern __shared__ char smem[];
    const uint32_t sb = smem_u32(smem);

    const int tid  = threadIdx.x;
    const int warp = tid >> 5, lane = tid & 31;
    const int wm   = warp >> 1, wn = warp & 1;     // 4 x 2 warp grid
    const int g    = lane >> 2, t = lane & 3;
    const int m0   = blockIdx.y * 128;
    const int n0   = blockIdx.x * 128;

    float acc[2][8][4];
    #pragma unroll
    for (int mi = 0; mi < 2; mi++)
        #pragma unroll
        for (int nj = 0; nj < 8; nj++)
            #pragma unroll
            for (int r = 0; r < 4; r++) acc[mi][nj][r] = 0.f;

    const char* gA = (const char*)A + (size_t)m0 * 768;   // 384 halfs/row
    const char* gB = (const char*)Bt + (size_t)n0 * 768;

    auto load_stage = [&](int kt, int s) {
        const uint32_t base = sb + s * STG_B;
        #pragma unroll
        for (int j = 0; j < 4; j++) {
            int c = tid + j * 256;
            int row = c >> 3, ch = c & 7;
            cp16(base + row * GSTRB + ch * 16,
                 gA + (size_t)row * 768 + kt * 128 + ch * 16);
        }
        #pragma unroll
        for (int j = 0; j < 4; j++) {
            int c = tid + j * 256;
            int row = c >> 3, ch = c & 7;
            cp16(base + TILE_B + row * GSTRB + ch * 16,
                 gB + (size_t)row * 768 + kt * 128 + ch * 16);
        }
    };

    auto compute = [&](int s) {
        const uint32_t aB = sb + s * STG_B;
        const uint32_t bB = aB + TILE_B;
        #pragma unroll
        for (int ks = 0; ks < 4; ks++) {
            uint32_t af[2][4], bf[8][2];
            #pragma unroll
            for (int mi = 0; mi < 2; mi++) {
                int mb = wm * 32 + mi * 16;
                uint32_t addr = aB + (mb + (lane & 15)) * GSTRB + ks * 32
                              + (lane >> 4) * 16;
                ldsm4(af[mi][0], af[mi][1], af[mi][2], af[mi][3], addr);
            }
            #pragma unroll
            for (int p = 0; p < 4; p++) {
                int j0 = wn * 64 + p * 16;
                uint32_t addr = bB + (j0 + (lane & 7) + ((lane >> 4) << 3)) * GSTRB
                              + ks * 32 + ((lane >> 3) & 1) * 16;
                ldsm4(bf[2 * p][0], bf[2 * p][1], bf[2 * p + 1][0],
                      bf[2 * p + 1][1], addr);
            }
            #pragma unroll
            for (int mi = 0; mi < 2; mi++)
                #pragma unroll
                for (int nj = 0; nj < 8; nj++)
                    mma_f16(acc[mi][nj], af[mi], bf[nj]);
        }
    };

    load_stage(0, 0); cp_commit();

    int s = 0;
    #pragma unroll 1
    for (int kt = 0; kt < 6; kt++) {
        if (kt + 1 < 6) { load_stage(kt + 1, s ^ 1); cp_commit(); }
        if (kt + 1 < 6) cp_wait1(); else cp_wait0();
        __syncthreads();
        compute(s);
        __syncthreads();
        s ^= 1;
    }

    #pragma unroll
    for (int mi = 0; mi < 2; mi++) {
        #pragma unroll
        for (int nj = 0; nj < 8; nj++) {
            int row = m0 + wm * 32 + mi * 16 + g;
            int col = n0 + wn * 64 + nj * 8 + 2 * t;
            float2 bb = *(const float2*)(bias + col);
            float a0 = acc[mi][nj][0] + bb.x, a1 = acc[mi][nj][1] + bb.y;
            float a2 = acc[mi][nj][2] + bb.x, a3 = acc[mi][nj][3] + bb.y;
            if (half_out) {
                __half* Ch = (__half*)C;
                *(uint32_t*)(Ch + (size_t)row * Ncols + col)       = packh2(a0, a1);
                *(uint32_t*)(Ch + (size_t)(row + 8) * Ncols + col) = packh2(a2, a3);
            } else {
                float* Cf = (float*)C;
                *(float2*)(Cf + (size_t)row * Ncols + col)       = make_float2(a0, a1);
                *(float2*)(Cf + (size_t)(row + 8) * Ncols + col) = make_float2(a2, a3);
            }
        }
    }
}

// ---------------------------------------------------------------------------
// fp16 tensor-core attention, 2 windows per block, double-buffered.
// Block = (window-pair, head-pair): 128 thr, 4 warps.
// Pipeline: issue loads(w0), loads(w1) as 2 cp.async groups; wait<=1 ->
// compute w0 (w1 loads in flight); wait 0 -> compute w1.
// Compute path = validated round-8 code, parameterized by buffer.
// ---------------------------------------------------------------------------
#define HST 40
__global__ void __launch_bounds__(128, 3)
attn_h_kernel(const __half* __restrict__ qkvh, const float* __restrict__ bias_g,
              __half* __restrict__ ctxh)
{
    __shared__ __align__(16) __half q_s[2][2][64 * HST];   // [buf][head]
    __shared__ __align__(16) __half k_s[2][2][64 * HST];
    __shared__ __align__(16) __half v_s[2][2][64 * HST];

    const int w0 = blockIdx.x * 2;
    const int hp = blockIdx.y;
    const int tid = threadIdx.x, wid = tid >> 5, lane = tid & 31;
    const int hh = wid >> 1, mwarp = wid & 1;
    const int h  = hp * 2 + hh;
    const int g  = lane >> 2, t = lane & 3;
    const float scale = 0.1767766952966369f;   // 32^-0.5
    const float* bh = bias_g + (size_t)h * (NTOK * NTOK);

    // issue loads for window w into buffer buf (zero pads + cp.async data)
    auto load_win = [&](int buf, int w) {
        uint4 z = make_uint4(0u, 0u, 0u, 0u);
        #pragma unroll
        for (int hl = 0; hl < 2; hl++) {
            for (int i = tid; i < 75; i += 128) {
                ((uint4*)(q_s[buf][hl] + 49 * HST))[i] = z;
                ((uint4*)(k_s[buf][hl] + 49 * HST))[i] = z;
                ((uint4*)(v_s[buf][hl] + 49 * HST))[i] = z;
            }
        }
        #pragma unroll
        for (int hl = 0; hl < 2; hl++) {
            const char* base = (const char*)(qkvh + (size_t)w * NTOK * N_QKV
                                             + (size_t)(hp * 2 + hl) * HDIM);
            uint32_t sq = smem_u32(q_s[buf][hl]);
            uint32_t sk = smem_u32(k_s[buf][hl]);
            uint32_t sv = smem_u32(v_s[buf][hl]);
            for (int idx = tid; idx < 588; idx += 128) {
                int mat = idx / 196, rem = idx - mat * 196;
                int r = rem >> 2, ch = rem & 3;
                uint32_t dst = (mat == 0 ? sq : mat == 1 ? sk : sv) + r * 80 + ch * 16;
                cp16(dst, base + (size_t)r * 2304 + mat * 768 + ch * 16);
            }
        }
    };

    auto compute_win = [&](int buf, int w) {
        const uint32_t Q = smem_u32(q_s[buf][hh]);
        const uint32_t K = smem_u32(k_s[buf][hh]);
        const uint32_t V = smem_u32(v_s[buf][hh]);

        // ---- S = Q K^T ----
        float sacc[2][8][4];
        #pragma unroll
        for (int mi = 0; mi < 2; mi++)
            #pragma unroll
            for (int nj = 0; nj < 8; nj++)
                #pragma unroll
                for (int r = 0; r < 4; r++) sacc[mi][nj][r] = 0.f;

        #pragma unroll
        for (int ks = 0; ks < 2; ks++) {
            uint32_t af[2][4], bf[8][2];
            #pragma unroll
            for (int mi = 0; mi < 2; mi++) {
                int mb = mwarp * 32 + mi * 16;
                uint32_t addr = Q + (mb + (lane & 15)) * 80 + ks * 32
                              + (lane >> 4) * 16;
                ldsm4(af[mi][0], af[mi][1], af[mi][2], af[mi][3], addr);
            }
            #pragma unroll
            for (int p = 0; p < 4; p++) {
                uint32_t addr = K + (p * 16 + (lane & 7) + ((lane >> 4) << 3)) * 80
                              + ks * 32 + ((lane >> 3) & 1) * 16;
                ldsm4(bf[2 * p][0], bf[2 * p][1], bf[2 * p + 1][0],
                      bf[2 * p + 1][1], addr);
            }
            #pragma unroll
            for (int mi = 0; mi < 2; mi++)
                #pragma unroll
                for (int nj = 0; nj < 8; nj++)
                    mma_f16(sacc[mi][nj], af[mi], bf[nj]);
        }

        // ---- scale + bias + column guard ----
        #pragma unroll
        for (int mi = 0; mi < 2; mi++) {
            int r0 = mwarp * 32 + mi * 16 + g;
            int r1 = r0 + 8;
            int br0 = min(r0, NTOK - 1) * NTOK;
            int br1 = min(r1, NTOK - 1) * NTOK;
            #pragma unroll
            for (int nj = 0; nj < 8; nj++) {
                int c0 = nj * 8 + 2 * t, c1 = c0 + 1;
                sacc[mi][nj][0] = (c0 < NTOK) ? sacc[mi][nj][0] * scale + bh[br0 + c0] : -1e30f;
                sacc[mi][nj][1] = (c1 < NTOK) ? sacc[mi][nj][1] * scale + bh[br0 + c1] : -1e30f;
                sacc[mi][nj][2] = (c0 < NTOK) ? sacc[mi][nj][2] * scale + bh[br1 + c0] : -1e30f;
                sacc[mi][nj][3] = (c1 < NTOK) ? sacc[mi][nj][3] * scale + bh[br1 + c1] : -1e30f;
            }
        }

        // ---- register softmax ----
        #pragma unroll
        for (int mi = 0; mi < 2; mi++) {
            float m0 = -1e30f, m1 = -1e30f;
            #pragma unroll
            for (int nj = 0; nj < 8; nj++) {
                m0 = fmaxf(m0, fmaxf(sacc[mi][nj][0], sacc[mi][nj][1]));
                m1 = fmaxf(m1, fmaxf(sacc[mi][nj][2], sacc[mi][nj][3]));
            }
            m0 = fmaxf(m0, __shfl_xor_sync(0xffffffffu, m0, 1));
            m0 = fmaxf(m0, __shfl_xor_sync(0xffffffffu, m0, 2));
            m1 = fmaxf(m1, __shfl_xor_sync(0xffffffffu, m1, 1));
            m1 = fmaxf(m1, __shfl_xor_sync(0xffffffffu, m1, 2));
            float s0 = 0.f, s1 = 0.f;
            #pragma unroll
            for (int nj = 0; nj < 8; nj++) {
                sacc[mi][nj][0] = __expf(sacc[mi][nj][0] - m0); s0 += sacc[mi][nj][0];
                sacc[mi][nj][1] = __expf(sacc[mi][nj][1] - m0); s0 += sacc[mi][nj][1];
                sacc[mi][nj][2] = __expf(sacc[mi][nj][2] - m1); s1 += sacc[mi][nj][2];
                sacc[mi][nj][3] = __expf(sacc[mi][nj][3] - m1); s1 += sacc[mi][nj][3];
            }
            s0 += __shfl_xor_sync(0xffffffffu, s0, 1);
            s0 += __shfl_xor_sync(0xffffffffu, s0, 2);
            s1 += __shfl_xor_sync(0xffffffffu, s1, 1);
            s1 += __shfl_xor_sync(0xffffffffu, s1, 2);
            float i0 = 1.f / s0, i1 = 1.f / s1;
            #pragma unroll
            for (int nj = 0; nj < 8; nj++) {
                sacc[mi][nj][0] *= i0; sacc[mi][nj][1] *= i0;
                sacc[mi][nj][2] *= i1; sacc[mi][nj][3] *= i1;
            }
        }

        // ---- O = P V ----
        float oacc[2][4][4];
        #pragma unroll
        for (int mi = 0; mi < 2; mi++)
            #pragma unroll
            for (int nd = 0; nd < 4; nd++)
                #pragma unroll
                for (int r = 0; r < 4; r++) oacc[mi][nd][r] = 0.f;

        #pragma unroll
        for (int jt = 0; jt < 4; jt++) {
            uint32_t bf[4][2];
            #pragma unroll
            for (int p = 0; p < 2; p++) {
                uint32_t addr = V + (jt * 16 + (lane & 7) + (((lane >> 3) & 1) << 3)) * 80
                              + p * 32 + ((lane >> 4) << 4);
                ldsm4t(bf[2 * p][0], bf[2 * p][1], bf[2 * p + 1][0],
                       bf[2 * p + 1][1], addr);
            }
            uint32_t pa[2][4];
            #pragma unroll
            for (int mi = 0; mi < 2; mi++) {
                pa[mi][0] = packh2(sacc[mi][2 * jt][0],     sacc[mi][2 * jt][1]);
                pa[mi][1] = packh2(sacc[mi][2 * jt][2],     sacc[mi][2 * jt][3]);
                pa[mi][2] = packh2(sacc[mi][2 * jt + 1][0], sacc[mi][2 * jt + 1][1]);
                pa[mi][3] = packh2(sacc[mi][2 * jt + 1][2], sacc[mi][2 * jt + 1][3]);
            }
            #pragma unroll
            for (int mi = 0; mi < 2; mi++)
                #pragma unroll
                for (int nd = 0; nd < 4; nd++)
                    mma_f16(oacc[mi][nd], pa[mi], bf[nd]);
        }

        // ---- store O ----
        #pragma unroll
        for (int mi = 0; mi < 2; mi++) {
            int r0 = mwarp * 32 + mi * 16 + g;
            int r1 = r0 + 8;
            #pragma unroll
            for (int nd = 0; nd < 4; nd++) {
                int d0 = nd * 8 + 2 * t;
                if (r0 < NTOK)
                    *(uint32_t*)(ctxh + ((size_t)w * NTOK + r0) * CDIM + h * HDIM + d0)
                        = packh2(oacc[mi][nd][0], oacc[mi][nd][1]);
                if (r1 < NTOK)
                    *(uint32_t*)(ctxh + ((size_t)w * NTOK + r1) * CDIM + h * HDIM + d0)
                        = packh2(oacc[mi][nd][2], oacc[mi][nd][3]);
            }
        }
    };

    load_win(0, w0);     cp_commit();
    load_win(1, w0 + 1); cp_commit();

    cp_wait1();            // buffer 0 complete (<=1 group pending)
    __syncthreads();
    compute_win(0, w0);

    cp_wait0();            // buffer 1 complete
    __syncthreads();
    compute_win(1, w0 + 1);
}

// ---------------------------------------------------------------------------
// Launch
// ---------------------------------------------------------------------------
extern "C" void kernel_launch(void* const* d_in, const int* in_sizes, int n_in,
                              void* d_out, int out_size)
{
    const float* x     = (const float*)d_in[0];
    const float* Wqkv  = (const float*)d_in[1];
    const float* bqkv  = (const float*)d_in[2];
    const float* Wproj = (const float*)d_in[3];
    const float* bproj = (const float*)d_in[4];
    const float* table = (const float*)d_in[5];
    const int*   relix = (const int*)d_in[6];
    float* out = (float*)d_out;

    __half *qkvh, *ctxh, *xh, *wqh, *wph;
    float* bias_g;
    cudaGetSymbolAddress((void**)&qkvh, g_qkvh);
    cudaGetSymbolAddress((void**)&ctxh, g_ctxh);
    cudaGetSymbolAddress((void**)&xh,   g_xh);
    cudaGetSymbolAddress((void**)&wqh,  g_wqh);
    cudaGetSymbolAddress((void**)&wph,  g_wph);
    cudaGetSymbolAddress((void**)&bias_g, g_bias);

    cudaFuncSetAttribute(gemm_f16_kernel,
                         cudaFuncAttributeMaxDynamicSharedMemorySize, GEMM_SMEM);

    // 0) prep
    f2h_kernel<<<4096, 256>>>((const float4*)x, (uint2*)xh, (MROWS * KDIM) / 4);
    transpose_h_kernel<<<dim3(N_QKV / 32, KDIM / 32), dim3(32, 8)>>>(
        Wqkv, wqh, KDIM, N_QKV);
    transpose_h_kernel<<<dim3(CDIM / 32, KDIM / 32), dim3(32, 8)>>>(
        Wproj, wph, KDIM, CDIM);
    bias_build_kernel<<<(HEADS * NTOK * NTOK + 255) / 256, 256>>>(
        table, relix, bias_g);

    // 1) qkv = half(x @ W_qkv + b)   (M=200704, N=1152, K=384)
    gemm_f16_kernel<<<dim3(N_QKV / 128, MROWS / 128), 256, GEMM_SMEM>>>(
        xh, wqh, bqkv, qkvh, N_QKV, 1);

    // 2) attention: one block per (window-pair, head-pair), double-buffered
    attn_h_kernel<<<dim3(BTOT / 2, HEADS / 2), 128>>>(qkvh, bias_g, ctxh);

    // 3) out = ctx @ W_proj + b      (M=200704, N=384, K=384), f32 out
    gemm_f16_kernel<<<dim3(CDIM / 128, MROWS / 128), 256, GEMM_SMEM>>>(
        ctxh, wph, bproj, out, CDIM, 0);
}

// round 14
// speedup vs baseline: 1.0626x; 1.0174x over previous
#include <cuda_runtime.h>
#include <cuda_fp16.h>
#include <cstdint>
#include <cstddef>

// ---------------------------------------------------------------------------
// Problem constants
// ---------------------------------------------------------------------------
#define BTOT   4096
#define NTOK   49
#define CDIM   384
#define HEADS  12
#define HDIM   32
#define MROWS  (BTOT * NTOK)        // 200704
#define KDIM   384
#define N_QKV  1152

// Scratch (__device__ globals: the allowed alloc-free pattern)
__device__ __half g_qkvh[(size_t)MROWS * N_QKV];  // 462 MB
__device__ __half g_ctxh[(size_t)MROWS * CDIM];   // 154 MB
__device__ __half g_xh  [(size_t)MROWS * KDIM];   // 154 MB
__device__ __half g_wqh [(size_t)N_QKV * KDIM];   // W_qkv^T as half [N][K]
__device__ __half g_wph [(size_t)CDIM * KDIM];    // W_proj^T as half [N][K]
__device__ float  g_bias[(size_t)HEADS * NTOK * NTOK];

// ---------------------------------------------------------------------------
// Helpers
// ---------------------------------------------------------------------------
__device__ __forceinline__ uint32_t smem_u32(const void* p) {
    return (uint32_t)__cvta_generic_to_shared(p);
}
__device__ __forceinline__ void cp16(uint32_t dst, const void* src) {
    asm volatile("cp.async.cg.shared.global [%0], [%1], 16;" :: "r"(dst), "l"(src));
}
__device__ __forceinline__ void cp_commit() {
    asm volatile("cp.async.commit_group;" ::: "memory");
}
__device__ __forceinline__ void cp_wait1() {
    asm volatile("cp.async.wait_group 1;" ::: "memory");
}
__device__ __forceinline__ void cp_wait0() {
    asm volatile("cp.async.wait_group 0;" ::: "memory");
}

__device__ __forceinline__ void ldsm4(uint32_t& r0, uint32_t& r1, uint32_t& r2,
                                      uint32_t& r3, uint32_t a) {
    asm volatile("ldmatrix.sync.aligned.m8n8.x4.shared.b16 {%0,%1,%2,%3}, [%4];"
                 : "=r"(r0), "=r"(r1), "=r"(r2), "=r"(r3) : "r"(a));
}
__device__ __forceinline__ void ldsm4t(uint32_t& r0, uint32_t& r1, uint32_t& r2,
                                       uint32_t& r3, uint32_t a) {
    asm volatile("ldmatrix.sync.aligned.m8n8.x4.trans.shared.b16 {%0,%1,%2,%3}, [%4];"
                 : "=r"(r0), "=r"(r1), "=r"(r2), "=r"(r3) : "r"(a));
}

__device__ __forceinline__ void mma_f16(float c[4], const uint32_t a[4],
                                        const uint32_t b[2]) {
    asm volatile(
        "mma.sync.aligned.m16n8k16.row.col.f32.f16.f16.f32 "
        "{%0,%1,%2,%3}, {%4,%5,%6,%7}, {%8,%9}, {%0,%1,%2,%3};"
        : "+f"(c[0]), "+f"(c[1]), "+f"(c[2]), "+f"(c[3])
        : "r"(a[0]), "r"(a[1]), "r"(a[2]), "r"(a[3]), "r"(b[0]), "r"(b[1]));
}

__device__ __forceinline__ uint32_t packh2(float lo, float hi) {
    __half2 h = __floats2half2_rn(lo, hi);
    return *(uint32_t*)&h;
}

// ---------------------------------------------------------------------------
// Prep kernels
// ---------------------------------------------------------------------------
// 8 floats per thread-iter, single 16B store
__global__ void f2h_kernel(const float4* __restrict__ in, uint4* __restrict__ out,
                           int n8)
{
    for (int i = blockIdx.x * blockDim.x + threadIdx.x; i < n8;
         i += gridDim.x * blockDim.x) {
        float4 a = in[2 * i], b = in[2 * i + 1];
        out[i] = make_uint4(packh2(a.x, a.y), packh2(a.z, a.w),
                            packh2(b.x, b.y), packh2(b.z, b.w));
    }
}

// Wt[n][k] = (half)W[k][n];  W is K x N row-major, K,N multiples of 32
__global__ void transpose_h_kernel(const float* __restrict__ W,
                                   __half* __restrict__ Wt, int K, int N)
{
    __shared__ float t[32][33];
    int kb = blockIdx.y * 32, nb = blockIdx.x * 32;
    int x = threadIdx.x, y = threadIdx.y;
    #pragma unroll
    for (int i = y; i < 32; i += 8)
        t[i][x] = W[(size_t)(kb + i) * N + nb + x];
    __syncthreads();
    #pragma unroll
    for (int i = y; i < 32; i += 8)
        Wt[(size_t)(nb + i) * K + kb + x] = __float2half_rn(t[x][i]);
}

__global__ void bias_build_kernel(const float* __restrict__ table,
                                  const int* __restrict__ relix,
                                  float* __restrict__ bias_g)
{
    int idx = blockIdx.x * blockDim.x + threadIdx.x;
    if (idx < HEADS * NTOK * NTOK) {
        int h = idx / (NTOK * NTOK), ij = idx % (NTOK * NTOK);
        bias_g[idx] = table[relix[ij] * HEADS + h];
    }
}

// ---------------------------------------------------------------------------
// fp16 GEMM (validated round-9 config): C = A_half @ Bt^T + bias
// CTA 128x128, 256 thr = 8 warps (4m x 2n), warp tile 32x64, BK=64.
// ---------------------------------------------------------------------------
#define GSTRB  144                    // smem row stride bytes (72 halfs)
#define TILE_B (128 * GSTRB)          // 18432 per operand tile
#define STG_B  (2 * TILE_B)           // 36864
#define GEMM_SMEM (2 * STG_B)         // 73728

__global__ void __launch_bounds__(256, 2)
gemm_f16_kernel(const __half* __restrict__ A, const __half* __restrict__ Bt,
                const float* __restrict__ bias, void* __restrict__ C,
                int Ncols, int half_out)
{
    extern __shared__ char smem[];
    const uint32_t sb = smem_u32(smem);

    const int tid  = threadIdx.x;
    const int warp = tid >> 5, lane = tid & 31;
    const int wm   = warp >> 1, wn = warp & 1;     // 4 x 2 warp grid
    const int g    = lane >> 2, t = lane & 3;
    const int m0   = blockIdx.y * 128;
    const int n0   = blockIdx.x * 128;

    float acc[2][8][4];
    #pragma unroll
    for (int mi = 0; mi < 2; mi++)
        #pragma unroll
        for (int nj = 0; nj < 8; nj++)
            #pragma unroll
            for (int r = 0; r < 4; r++) acc[mi][nj][r] = 0.f;

    const char* gA = (const char*)A + (size_t)m0 * 768;   // 384 halfs/row
    const char* gB = (const char*)Bt + (size_t)n0 * 768;

    auto load_stage = [&](int kt, int s) {
        const uint32_t base = sb + s * STG_B;
        #pragma unroll
        for (int j = 0; j < 4; j++) {
            int c = tid + j * 256;
            int row = c >> 3, ch = c & 7;
            cp16(base + row * GSTRB + ch * 16,
                 gA + (size_t)row * 768 + kt * 128 + ch * 16);
        }
        #pragma unroll
        for (int j = 0; j < 4; j++) {
            int c = tid + j * 256;
            int row = c >> 3, ch = c & 7;
            cp16(base + TILE_B + row * GSTRB + ch * 16,
                 gB + (size_t)row * 768 + kt * 128 + ch * 16);
        }
    };

    auto compute = [&](int s) {
        const uint32_t aB = sb + s * STG_B;
        const uint32_t bB = aB + TILE_B;
        #pragma unroll
        for (int ks = 0; ks < 4; ks++) {
            uint32_t af[2][4], bf[8][2];
            #pragma unroll
            for (int mi = 0; mi < 2; mi++) {
                int mb = wm * 32 + mi * 16;
                uint32_t addr = aB + (mb + (lane & 15)) * GSTRB + ks * 32
                              + (lane >> 4) * 16;
                ldsm4(af[mi][0], af[mi][1], af[mi][2], af[mi][3], addr);
            }
            #pragma unroll
            for (int p = 0; p < 4; p++) {
                int j0 = wn * 64 + p * 16;
                uint32_t addr = bB + (j0 + (lane & 7) + ((lane >> 4) << 3)) * GSTRB
                              + ks * 32 + ((lane >> 3) & 1) * 16;
                ldsm4(bf[2 * p][0], bf[2 * p][1], bf[2 * p + 1][0],
                      bf[2 * p + 1][1], addr);
            }
            #pragma unroll
            for (int mi = 0; mi < 2; mi++)
                #pragma unroll
                for (int nj = 0; nj < 8; nj++)
                    mma_f16(acc[mi][nj], af[mi], bf[nj]);
        }
    };

    load_stage(0, 0); cp_commit();

    int s = 0;
    #pragma unroll 1
    for (int kt = 0; kt < 6; kt++) {
        if (kt + 1 < 6) { load_stage(kt + 1, s ^ 1); cp_commit(); }
        if (kt + 1 < 6) cp_wait1(); else cp_wait0();
        __syncthreads();
        compute(s);
        __syncthreads();
        s ^= 1;
    }

    #pragma unroll
    for (int mi = 0; mi < 2; mi++) {
        #pragma unroll
        for (int nj = 0; nj < 8; nj++) {
            int row = m0 + wm * 32 + mi * 16 + g;
            int col = n0 + wn * 64 + nj * 8 + 2 * t;
            float2 bb = *(const float2*)(bias + col);
            float a0 = acc[mi][nj][0] + bb.x, a1 = acc[mi][nj][1] + bb.y;
            float a2 = acc[mi][nj][2] + bb.x, a3 = acc[mi][nj][3] + bb.y;
            if (half_out) {
                __half* Ch = (__half*)C;
                *(uint32_t*)(Ch + (size_t)row * Ncols + col)       = packh2(a0, a1);
                *(uint32_t*)(Ch + (size_t)(row + 8) * Ncols + col) = packh2(a2, a3);
            } else {
                float* Cf = (float*)C;
                *(float2*)(Cf + (size_t)row * Ncols + col)       = make_float2(a0, a1);
                *(float2*)(Cf + (size_t)(row + 8) * Ncols + col) = make_float2(a2, a3);
            }
        }
    }
}

// ---------------------------------------------------------------------------
// fp16 tensor-core attention (slimmed): 7 N-tiles (K padded to 56, not 64),
// no softmax max-subtraction (inputs bounded), guards only in tile 6.
// Block = (window, head-pair): 128 thr, 4 warps.
// ---------------------------------------------------------------------------
#define HST 40
__global__ void __launch_bounds__(128, 4)
attn_h_kernel(const __half* __restrict__ qkvh, const float* __restrict__ bias_g,
              __half* __restrict__ ctxh)
{
    __shared__ __align__(16) __half q_s[2][64 * HST];
    __shared__ __align__(16) __half k_s[2][64 * HST];
    __shared__ __align__(16) __half v_s[2][64 * HST];

    const int w  = blockIdx.x;
    const int hp = blockIdx.y;
    const int tid = threadIdx.x, wid = tid >> 5, lane = tid & 31;
    const int hh = wid >> 1, mwarp = wid & 1;
    const int h  = hp * 2 + hh;
    const int g  = lane >> 2, t = lane & 3;
    const float scale = 0.1767766952966369f;   // 32^-0.5

    // zero pads: q rows 49..63 (A operand), k/v rows 49..55 (K dim = 56)
    #pragma unroll
    for (int hl = 0; hl < 2; hl++) {
        uint4 z = make_uint4(0u, 0u, 0u, 0u);
        for (int i = tid; i < 75; i += 128)
            ((uint4*)(q_s[hl] + 49 * HST))[i] = z;
        for (int i = tid; i < 35; i += 128) {
            ((uint4*)(k_s[hl] + 49 * HST))[i] = z;
            ((uint4*)(v_s[hl] + 49 * HST))[i] = z;
        }
    }

    #pragma unroll
    for (int hl = 0; hl < 2; hl++) {
        const char* base = (const char*)(qkvh + (size_t)w * NTOK * N_QKV
                                         + (size_t)(hp * 2 + hl) * HDIM);
        uint32_t sq = smem_u32(q_s[hl]), sk = smem_u32(k_s[hl]), sv = smem_u32(v_s[hl]);
        for (int idx = tid; idx < 588; idx += 128) {
            int mat = idx / 196, rem = idx - mat * 196;
            int r = rem >> 2, ch = rem & 3;
            uint32_t dst = (mat == 0 ? sq : mat == 1 ? sk : sv) + r * 80 + ch * 16;
            cp16(dst, base + (size_t)r * 2304 + mat * 768 + ch * 16);
        }
    }
    cp_commit();
    cp_wait0();
    __syncthreads();

    const uint32_t Q = smem_u32(q_s[hh]);
    const uint32_t K = smem_u32(k_s[hh]);
    const uint32_t V = smem_u32(v_s[hh]);

    // ---- S = Q K^T : 2 k-steps x 2 m-tiles x 7 n-tiles ----
    float sacc[2][7][4];
    #pragma unroll
    for (int mi = 0; mi < 2; mi++)
        #pragma unroll
        for (int nj = 0; nj < 7; nj++)
            #pragma unroll
            for (int r = 0; r < 4; r++) sacc[mi][nj][r] = 0.f;

    #pragma unroll
    for (int ks = 0; ks < 2; ks++) {
        uint32_t af[2][4], bf[8][2];
        #pragma unroll
        for (int mi = 0; mi < 2; mi++) {
            int mb = mwarp * 32 + mi * 16;
            uint32_t addr = Q + (mb + (lane & 15)) * 80 + ks * 32 + (lane >> 4) * 16;
            ldsm4(af[mi][0], af[mi][1], af[mi][2], af[mi][3], addr);
        }
        #pragma unroll
        for (int p = 0; p < 4; p++) {     // loads tiles 2p, 2p+1 (tile 7 unused)
            uint32_t addr = K + (p * 16 + (lane & 7) + ((lane >> 4) << 3)) * 80
                          + ks * 32 + ((lane >> 3) & 1) * 16;
            ldsm4(bf[2 * p][0], bf[2 * p][1], bf[2 * p + 1][0], bf[2 * p + 1][1], addr);
        }
        #pragma unroll
        for (int mi = 0; mi < 2; mi++)
            #pragma unroll
            for (int nj = 0; nj < 7; nj++)
                mma_f16(sacc[mi][nj], af[mi], bf[nj]);
    }

    // ---- scale + bias; guards only in tile 6 (cols 48..55) ----
    const float* bh = bias_g + (size_t)h * (NTOK * NTOK);
    #pragma unroll
    for (int mi = 0; mi < 2; mi++) {
        int r0 = mwarp * 32 + mi * 16 + g;
        int r1 = r0 + 8;
        int br0 = min(r0, NTOK - 1) * NTOK;
        int br1 = min(r1, NTOK - 1) * NTOK;
        #pragma unroll
        for (int nj = 0; nj < 6; nj++) {
            int c0 = nj * 8 + 2 * t;
            sacc[mi][nj][0] = sacc[mi][nj][0] * scale + bh[br0 + c0];
            sacc[mi][nj][1] = sacc[mi][nj][1] * scale + bh[br0 + c0 + 1];
            sacc[mi][nj][2] = sacc[mi][nj][2] * scale + bh[br1 + c0];
            sacc[mi][nj][3] = sacc[mi][nj][3] * scale + bh[br1 + c0 + 1];
        }
        // tile 6: col 48 real only for t==0 lanes; cols 49..55 padded
        if (t == 0) {
            sacc[mi][6][0] = sacc[mi][6][0] * scale + bh[br0 + 48];
            sacc[mi][6][2] = sacc[mi][6][2] * scale + bh[br1 + 48];
        } else {
            sacc[mi][6][0] = -1e30f;
            sacc[mi][6][2] = -1e30f;
        }
        sacc[mi][6][1] = -1e30f;
        sacc[mi][6][3] = -1e30f;
    }

    // ---- softmax, no max-subtraction (|S| bounded ~10) ----
    #pragma unroll
    for (int mi = 0; mi < 2; mi++) {
        float s0 = 0.f, s1 = 0.f;
        #pragma unroll
        for (int nj = 0; nj < 7; nj++) {
            sacc[mi][nj][0] = __expf(sacc[mi][nj][0]); s0 += sacc[mi][nj][0];
            sacc[mi][nj][1] = __expf(sacc[mi][nj][1]); s0 += sacc[mi][nj][1];
            sacc[mi][nj][2] = __expf(sacc[mi][nj][2]); s1 += sacc[mi][nj][2];
            sacc[mi][nj][3] = __expf(sacc[mi][nj][3]); s1 += sacc[mi][nj][3];
        }
        s0 += __shfl_xor_sync(0xffffffffu, s0, 1);
        s0 += __shfl_xor_sync(0xffffffffu, s0, 2);
        s1 += __shfl_xor_sync(0xffffffffu, s1, 1);
        s1 += __shfl_xor_sync(0xffffffffu, s1, 2);
        float i0 = 1.f / s0, i1 = 1.f / s1;
        #pragma unroll
        for (int nj = 0; nj < 7; nj++) {
            sacc[mi][nj][0] *= i0; sacc[mi][nj][1] *= i0;
            sacc[mi][nj][2] *= i1; sacc[mi][nj][3] *= i1;
        }
    }

    // ---- O = P V : jt=3 feeds tile 6 + zeros (tile 7 absent) ----
    float oacc[2][4][4];
    #pragma unroll
    for (int mi = 0; mi < 2; mi++)
        #pragma unroll
        for (int nd = 0; nd < 4; nd++)
            #pragma unroll
            for (int r = 0; r < 4; r++) oacc[mi][nd][r] = 0.f;

    #pragma unroll
    for (int jt = 0; jt < 4; jt++) {
        uint32_t bf[4][2];
        #pragma unroll
        for (int p = 0; p < 2; p++) {
            uint32_t addr = V + (jt * 16 + (lane & 7) + (((lane >> 3) & 1) << 3)) * 80
                          + p * 32 + ((lane >> 4) << 4);
            ldsm4t(bf[2 * p][0], bf[2 * p][1], bf[2 * p + 1][0], bf[2 * p + 1][1], addr);
        }
        uint32_t pa[2][4];
        #pragma unroll
        for (int mi = 0; mi < 2; mi++) {
            pa[mi][0] = packh2(sacc[mi][2 * jt][0], sacc[mi][2 * jt][1]);
            pa[mi][1] = packh2(sacc[mi][2 * jt][2], sacc[mi][2 * jt][3]);
            if (jt < 3) {
                pa[mi][2] = packh2(sacc[mi][2 * jt + 1][0], sacc[mi][2 * jt + 1][1]);
                pa[mi][3] = packh2(sacc[mi][2 * jt + 1][2], sacc[mi][2 * jt + 1][3]);
            } else {
                pa[mi][2] = 0u;
                pa[mi][3] = 0u;
            }
        }
        #pragma unroll
        for (int mi = 0; mi < 2; mi++)
            #pragma unroll
            for (int nd = 0; nd < 4; nd++)
                mma_f16(oacc[mi][nd], pa[mi], bf[nd]);
    }

    // ---- store O ----
    #pragma unroll
    for (int mi = 0; mi < 2; mi++) {
        int r0 = mwarp * 32 + mi * 16 + g;
        int r1 = r0 + 8;
        #pragma unroll
        for (int nd = 0; nd < 4; nd++) {
            int d0 = nd * 8 + 2 * t;
            if (r0 < NTOK)
                *(uint32_t*)(ctxh + ((size_t)w * NTOK + r0) * CDIM + h * HDIM + d0)
                    = packh2(oacc[mi][nd][0], oacc[mi][nd][1]);
            if (r1 < NTOK)
                *(uint32_t*)(ctxh + ((size_t)w * NTOK + r1) * CDIM + h * HDIM + d0)
                    = packh2(oacc[mi][nd][2], oacc[mi][nd][3]);
        }
    }
}

// ---------------------------------------------------------------------------
// Launch
// ---------------------------------------------------------------------------
extern "C" void kernel_launch(void* const* d_in, const int* in_sizes, int n_in,
                              void* d_out, int out_size)
{
    const float* x     = (const float*)d_in[0];
    const float* Wqkv  = (const float*)d_in[1];
    const float* bqkv  = (const float*)d_in[2];
    const float* Wproj = (const float*)d_in[3];
    const float* bproj = (const float*)d_in[4];
    const float* table = (const float*)d_in[5];
    const int*   relix = (const int*)d_in[6];
    float* out = (float*)d_out;

    __half *qkvh, *ctxh, *xh, *wqh, *wph;
    float* bias_g;
    cudaGetSymbolAddress((void**)&qkvh, g_qkvh);
    cudaGetSymbolAddress((void**)&ctxh, g_ctxh);
    cudaGetSymbolAddress((void**)&xh,   g_xh);
    cudaGetSymbolAddress((void**)&wqh,  g_wqh);
    cudaGetSymbolAddress((void**)&wph,  g_wph);
    cudaGetSymbolAddress((void**)&bias_g, g_bias);

    cudaFuncSetAttribute(gemm_f16_kernel,
                         cudaFuncAttributeMaxDynamicSharedMemorySize, GEMM_SMEM);

    // 0) prep
    f2h_kernel<<<4096, 256>>>((const float4*)x, (uint4*)xh, (MROWS * KDIM) / 8);
    transpose_h_kernel<<<dim3(N_QKV / 32, KDIM / 32), dim3(32, 8)>>>(
        Wqkv, wqh, KDIM, N_QKV);
    transpose_h_kernel<<<dim3(CDIM / 32, KDIM / 32), dim3(32, 8)>>>(
        Wproj, wph, KDIM, CDIM);
    bias_build_kernel<<<(HEADS * NTOK * NTOK + 255) / 256, 256>>>(
        table, relix, bias_g);

    // 1) qkv = half(x @ W_qkv + b)   (M=200704, N=1152, K=384)
    gemm_f16_kernel<<<dim3(N_QKV / 128, MROWS / 128), 256, GEMM_SMEM>>>(
        xh, wqh, bqkv, qkvh, N_QKV, 1);

    // 2) attention (fp16 tensor-core), one block per (window, head-pair)
    attn_h_kernel<<<dim3(BTOT, HEADS / 2), 128>>>(qkvh, bias_g, ctxh);

    // 3) out = ctx @ W_proj + b      (M=200704, N=384, K=384), f32 out
    gemm_f16_kernel<<<dim3(CDIM / 128, MROWS / 128), 256, GEMM_SMEM>>>(
        ctxh, wph, bproj, out, CDIM, 0);
}

// round 15
// speedup vs baseline: 1.1052x; 1.0401x over previous
#include <cuda_runtime.h>
#include <cuda_fp16.h>
#include <cstdint>
#include <cstddef>

// ---------------------------------------------------------------------------
// Problem constants
// ---------------------------------------------------------------------------
#define BTOT   4096
#define NTOK   49
#define CDIM   384
#define HEADS  12
#define HDIM   32
#define MROWS  (BTOT * NTOK)        // 200704
#define KDIM   384
#define N_QKV  1152

// Scratch (__device__ globals: the allowed alloc-free pattern)
__device__ __half g_qkvh[(size_t)MROWS * N_QKV];  // 462 MB
__device__ __half g_ctxh[(size_t)MROWS * CDIM];   // 154 MB
__device__ __half g_xh  [(size_t)MROWS * KDIM];   // 154 MB
__device__ __half g_wqh [(size_t)N_QKV * KDIM];   // W_qkv^T as half [N][K]
__device__ __half g_wph [(size_t)CDIM * KDIM];    // W_proj^T as half [N][K]
__device__ float  g_bias[(size_t)HEADS * NTOK * NTOK];

// ---------------------------------------------------------------------------
// Helpers
// ---------------------------------------------------------------------------
__device__ __forceinline__ uint32_t smem_u32(const void* p) {
    return (uint32_t)__cvta_generic_to_shared(p);
}
__device__ __forceinline__ void cp16(uint32_t dst, const void* src) {
    asm volatile("cp.async.cg.shared.global [%0], [%1], 16;" :: "r"(dst), "l"(src));
}
__device__ __forceinline__ void cp_commit() {
    asm volatile("cp.async.commit_group;" ::: "memory");
}
__device__ __forceinline__ void cp_wait0() {
    asm volatile("cp.async.wait_group 0;" ::: "memory");
}

__device__ __forceinline__ void ldsm4(uint32_t& r0, uint32_t& r1, uint32_t& r2,
                                      uint32_t& r3, uint32_t a) {
    asm volatile("ldmatrix.sync.aligned.m8n8.x4.shared.b16 {%0,%1,%2,%3}, [%4];"
                 : "=r"(r0), "=r"(r1), "=r"(r2), "=r"(r3) : "r"(a));
}
__device__ __forceinline__ void ldsm4t(uint32_t& r0, uint32_t& r1, uint32_t& r2,
                                       uint32_t& r3, uint32_t a) {
    asm volatile("ldmatrix.sync.aligned.m8n8.x4.trans.shared.b16 {%0,%1,%2,%3}, [%4];"
                 : "=r"(r0), "=r"(r1), "=r"(r2), "=r"(r3) : "r"(a));
}

__device__ __forceinline__ void mma_f16(float c[4], const uint32_t a[4],
                                        const uint32_t b[2]) {
    asm volatile(
        "mma.sync.aligned.m16n8k16.row.col.f32.f16.f16.f32 "
        "{%0,%1,%2,%3}, {%4,%5,%6,%7}, {%8,%9}, {%0,%1,%2,%3};"
        : "+f"(c[0]), "+f"(c[1]), "+f"(c[2]), "+f"(c[3])
        : "r"(a[0]), "r"(a[1]), "r"(a[2]), "r"(a[3]), "r"(b[0]), "r"(b[1]));
}

__device__ __forceinline__ uint32_t packh2(float lo, float hi) {
    __half2 h = __floats2half2_rn(lo, hi);
    return *(uint32_t*)&h;
}

// ---------------------------------------------------------------------------
// Prep kernels
// ---------------------------------------------------------------------------
__global__ void f2h_kernel(const float4* __restrict__ in, uint4* __restrict__ out,
                           int n8)
{
    for (int i = blockIdx.x * blockDim.x + threadIdx.x; i < n8;
         i += gridDim.x * blockDim.x) {
        float4 a = in[2 * i], b = in[2 * i + 1];
        out[i] = make_uint4(packh2(a.x, a.y), packh2(a.z, a.w),
                            packh2(b.x, b.y), packh2(b.z, b.w));
    }
}

// Wt[n][k] = (half)W[k][n];  W is K x N row-major, K,N multiples of 32
__global__ void transpose_h_kernel(const float* __restrict__ W,
                                   __half* __restrict__ Wt, int K, int N)
{
    __shared__ float t[32][33];
    int kb = blockIdx.y * 32, nb = blockIdx.x * 32;
    int x = threadIdx.x, y = threadIdx.y;
    #pragma unroll
    for (int i = y; i < 32; i += 8)
        t[i][x] = W[(size_t)(kb + i) * N + nb + x];
    __syncthreads();
    #pragma unroll
    for (int i = y; i < 32; i += 8)
        Wt[(size_t)(nb + i) * K + kb + x] = __float2half_rn(t[x][i]);
}

__global__ void bias_build_kernel(const float* __restrict__ table,
                                  const int* __restrict__ relix,
                                  float* __restrict__ bias_g)
{
    int idx = blockIdx.x * blockDim.x + threadIdx.x;
    if (idx < HEADS * NTOK * NTOK) {
        int h = idx / (NTOK * NTOK), ij = idx % (NTOK * NTOK);
        bias_g[idx] = table[relix[ij] * HEADS + h];
    }
}

// ---------------------------------------------------------------------------
// fp16 GEMM: C = A_half @ Bt^T + bias
// CTA 128x128, 256 thr = 8 warps (4m x 2n), warp tile 32x64, BK=64.
// SINGLE-sync pipeline: wait0 -> sync -> issue next loads -> compute.
// (hazard proof in header comment of this round's analysis)
// ---------------------------------------------------------------------------
#define GSTRB  144                    // smem row stride bytes (72 halfs)
#define TILE_B (128 * GSTRB)          // 18432 per operand tile
#define STG_B  (2 * TILE_B)           // 36864
#define GEMM_SMEM (2 * STG_B)         // 73728

__global__ void __launch_bounds__(256, 2)
gemm_f16_kernel(const __half* __restrict__ A, const __half* __restrict__ Bt,
                const float* __restrict__ bias, void* __restrict__ C,
                int Ncols, int half_out)
{
    extern __shared__ char smem[];
    const uint32_t sb = smem_u32(smem);

    const int tid  = threadIdx.x;
    const int warp = tid >> 5, lane = tid & 31;
    const int wm   = warp >> 1, wn = warp & 1;     // 4 x 2 warp grid
    const int g    = lane >> 2, t = lane & 3;
    const int m0   = blockIdx.y * 128;
    const int n0   = blockIdx.x * 128;

    float acc[2][8][4];
    #pragma unroll
    for (int mi = 0; mi < 2; mi++)
        #pragma unroll
        for (int nj = 0; nj < 8; nj++)
            #pragma unroll
            for (int r = 0; r < 4; r++) acc[mi][nj][r] = 0.f;

    const char* gA = (const char*)A + (size_t)m0 * 768;   // 384 halfs/row
    const char* gB = (const char*)Bt + (size_t)n0 * 768;

    auto load_stage = [&](int kt, int s) {
        const uint32_t base = sb + s * STG_B;
        #pragma unroll
        for (int j = 0; j < 4; j++) {
            int c = tid + j * 256;
            int row = c >> 3, ch = c & 7;
            cp16(base + row * GSTRB + ch * 16,
                 gA + (size_t)row * 768 + kt * 128 + ch * 16);
        }
        #pragma unroll
        for (int j = 0; j < 4; j++) {
            int c = tid + j * 256;
            int row = c >> 3, ch = c & 7;
            cp16(base + TILE_B + row * GSTRB + ch * 16,
                 gB + (size_t)row * 768 + kt * 128 + ch * 16);
        }
    };

    auto compute = [&](int s) {
        const uint32_t aB = sb + s * STG_B;
        const uint32_t bB = aB + TILE_B;
        #pragma unroll
        for (int ks = 0; ks < 4; ks++) {
            uint32_t af[2][4], bf[8][2];
            #pragma unroll
            for (int mi = 0; mi < 2; mi++) {
                int mb = wm * 32 + mi * 16;
                uint32_t addr = aB + (mb + (lane & 15)) * GSTRB + ks * 32
                              + (lane >> 4) * 16;
                ldsm4(af[mi][0], af[mi][1], af[mi][2], af[mi][3], addr);
            }
            #pragma unroll
            for (int p = 0; p < 4; p++) {
                int j0 = wn * 64 + p * 16;
                uint32_t addr = bB + (j0 + (lane & 7) + ((lane >> 4) << 3)) * GSTRB
                              + ks * 32 + ((lane >> 3) & 1) * 16;
                ldsm4(bf[2 * p][0], bf[2 * p][1], bf[2 * p + 1][0],
                      bf[2 * p + 1][1], addr);
            }
            #pragma unroll
            for (int mi = 0; mi < 2; mi++)
                #pragma unroll
                for (int nj = 0; nj < 8; nj++)
                    mma_f16(acc[mi][nj], af[mi], bf[nj]);
        }
    };

    load_stage(0, 0); cp_commit();

    // single-sync pipeline:
    //   wait0: drain group kt (only pending group)
    //   sync : all warps retired compute(s^1) of iter kt-1
    //   issue loads kt+1 into s^1 (overwrite-safe by the sync above)
    //   compute(s)
    #pragma unroll 1
    for (int kt = 0; kt < 6; kt++) {
        int s = kt & 1;
        cp_wait0();
        __syncthreads();
        if (kt + 1 < 6) { load_stage(kt + 1, s ^ 1); cp_commit(); }
        compute(s);
    }

    #pragma unroll
    for (int mi = 0; mi < 2; mi++) {
        #pragma unroll
        for (int nj = 0; nj < 8; nj++) {
            int row = m0 + wm * 32 + mi * 16 + g;
            int col = n0 + wn * 64 + nj * 8 + 2 * t;
            float2 bb = *(const float2*)(bias + col);
            float a0 = acc[mi][nj][0] + bb.x, a1 = acc[mi][nj][1] + bb.y;
            float a2 = acc[mi][nj][2] + bb.x, a3 = acc[mi][nj][3] + bb.y;
            if (half_out) {
                __half* Ch = (__half*)C;
                *(uint32_t*)(Ch + (size_t)row * Ncols + col)       = packh2(a0, a1);
                *(uint32_t*)(Ch + (size_t)(row + 8) * Ncols + col) = packh2(a2, a3);
            } else {
                float* Cf = (float*)C;
                *(float2*)(Cf + (size_t)row * Ncols + col)       = make_float2(a0, a1);
                *(float2*)(Cf + (size_t)(row + 8) * Ncols + col) = make_float2(a2, a3);
            }
        }
    }
}

// ---------------------------------------------------------------------------
// fp16 tensor-core attention (validated round-14 version, unchanged):
// 7 N-tiles, no max-subtraction, guards only in tile 6.
// Block = (window, head-pair): 128 thr, 4 warps.
// ---------------------------------------------------------------------------
#define HST 40
__global__ void __launch_bounds__(128, 4)
attn_h_kernel(const __half* __restrict__ qkvh, const float* __restrict__ bias_g,
              __half* __restrict__ ctxh)
{
    __shared__ __align__(16) __half q_s[2][64 * HST];
    __shared__ __align__(16) __half k_s[2][64 * HST];
    __shared__ __align__(16) __half v_s[2][64 * HST];

    const int w  = blockIdx.x;
    const int hp = blockIdx.y;
    const int tid = threadIdx.x, wid = tid >> 5, lane = tid & 31;
    const int hh = wid >> 1, mwarp = wid & 1;
    const int h  = hp * 2 + hh;
    const int g  = lane >> 2, t = lane & 3;
    const float scale = 0.1767766952966369f;   // 32^-0.5

    #pragma unroll
    for (int hl = 0; hl < 2; hl++) {
        uint4 z = make_uint4(0u, 0u, 0u, 0u);
        for (int i = tid; i < 75; i += 128)
            ((uint4*)(q_s[hl] + 49 * HST))[i] = z;
        for (int i = tid; i < 35; i += 128) {
            ((uint4*)(k_s[hl] + 49 * HST))[i] = z;
            ((uint4*)(v_s[hl] + 49 * HST))[i] = z;
        }
    }

    #pragma unroll
    for (int hl = 0; hl < 2; hl++) {
        const char* base = (const char*)(qkvh + (size_t)w * NTOK * N_QKV
                                         + (size_t)(hp * 2 + hl) * HDIM);
        uint32_t sq = smem_u32(q_s[hl]), sk = smem_u32(k_s[hl]), sv = smem_u32(v_s[hl]);
        for (int idx = tid; idx < 588; idx += 128) {
            int mat = idx / 196, rem = idx - mat * 196;
            int r = rem >> 2, ch = rem & 3;
            uint32_t dst = (mat == 0 ? sq : mat == 1 ? sk : sv) + r * 80 + ch * 16;
            cp16(dst, base + (size_t)r * 2304 + mat * 768 + ch * 16);
        }
    }
    cp_commit();
    cp_wait0();
    __syncthreads();

    const uint32_t Q = smem_u32(q_s[hh]);
    const uint32_t K = smem_u32(k_s[hh]);
    const uint32_t V = smem_u32(v_s[hh]);

    float sacc[2][7][4];
    #pragma unroll
    for (int mi = 0; mi < 2; mi++)
        #pragma unroll
        for (int nj = 0; nj < 7; nj++)
            #pragma unroll
            for (int r = 0; r < 4; r++) sacc[mi][nj][r] = 0.f;

    #pragma unroll
    for (int ks = 0; ks < 2; ks++) {
        uint32_t af[2][4], bf[8][2];
        #pragma unroll
        for (int mi = 0; mi < 2; mi++) {
            int mb = mwarp * 32 + mi * 16;
            uint32_t addr = Q + (mb + (lane & 15)) * 80 + ks * 32 + (lane >> 4) * 16;
            ldsm4(af[mi][0], af[mi][1], af[mi][2], af[mi][3], addr);
        }
        #pragma unroll
        for (int p = 0; p < 4; p++) {
            uint32_t addr = K + (p * 16 + (lane & 7) + ((lane >> 4) << 3)) * 80
                          + ks * 32 + ((lane >> 3) & 1) * 16;
            ldsm4(bf[2 * p][0], bf[2 * p][1], bf[2 * p + 1][0], bf[2 * p + 1][1], addr);
        }
        #pragma unroll
        for (int mi = 0; mi < 2; mi++)
            #pragma unroll
            for (int nj = 0; nj < 7; nj++)
                mma_f16(sacc[mi][nj], af[mi], bf[nj]);
    }

    const float* bh = bias_g + (size_t)h * (NTOK * NTOK);
    #pragma unroll
    for (int mi = 0; mi < 2; mi++) {
        int r0 = mwarp * 32 + mi * 16 + g;
        int r1 = r0 + 8;
        int br0 = min(r0, NTOK - 1) * NTOK;
        int br1 = min(r1, NTOK - 1) * NTOK;
        #pragma unroll
        for (int nj = 0; nj < 6; nj++) {
            int c0 = nj * 8 + 2 * t;
            sacc[mi][nj][0] = sacc[mi][nj][0] * scale + bh[br0 + c0];
            sacc[mi][nj][1] = sacc[mi][nj][1] * scale + bh[br0 + c0 + 1];
            sacc[mi][nj][2] = sacc[mi][nj][2] * scale + bh[br1 + c0];
            sacc[mi][nj][3] = sacc[mi][nj][3] * scale + bh[br1 + c0 + 1];
        }
        if (t == 0) {
            sacc[mi][6][0] = sacc[mi][6][0] * scale + bh[br0 + 48];
            sacc[mi][6][2] = sacc[mi][6][2] * scale + bh[br1 + 48];
        } else {
            sacc[mi][6][0] = -1e30f;
            sacc[mi][6][2] = -1e30f;
        }
        sacc[mi][6][1] = -1e30f;
        sacc[mi][6][3] = -1e30f;
    }

    #pragma unroll
    for (int mi = 0; mi < 2; mi++) {
        float s0 = 0.f, s1 = 0.f;
        #pragma unroll
        for (int nj = 0; nj < 7; nj++) {
            sacc[mi][nj][0] = __expf(sacc[mi][nj][0]); s0 += sacc[mi][nj][0];
            sacc[mi][nj][1] = __expf(sacc[mi][nj][1]); s0 += sacc[mi][nj][1];
            sacc[mi][nj][2] = __expf(sacc[mi][nj][2]); s1 += sacc[mi][nj][2];
            sacc[mi][nj][3] = __expf(sacc[mi][nj][3]); s1 += sacc[mi][nj][3];
        }
        s0 += __shfl_xor_sync(0xffffffffu, s0, 1);
        s0 += __shfl_xor_sync(0xffffffffu, s0, 2);
        s1 += __shfl_xor_sync(0xffffffffu, s1, 1);
        s1 += __shfl_xor_sync(0xffffffffu, s1, 2);
        float i0 = 1.f / s0, i1 = 1.f / s1;
        #pragma unroll
        for (int nj = 0; nj < 7; nj++) {
            sacc[mi][nj][0] *= i0; sacc[mi][nj][1] *= i0;
            sacc[mi][nj][2] *= i1; sacc[mi][nj][3] *= i1;
        }
    }

    float oacc[2][4][4];
    #pragma unroll
    for (int mi = 0; mi < 2; mi++)
        #pragma unroll
        for (int nd = 0; nd < 4; nd++)
            #pragma unroll
            for (int r = 0; r < 4; r++) oacc[mi][nd][r] = 0.f;

    #pragma unroll
    for (int jt = 0; jt < 4; jt++) {
        uint32_t bf[4][2];
        #pragma unroll
        for (int p = 0; p < 2; p++) {
            uint32_t addr = V + (jt * 16 + (lane & 7) + (((lane >> 3) & 1) << 3)) * 80
                          + p * 32 + ((lane >> 4) << 4);
            ldsm4t(bf[2 * p][0], bf[2 * p][1], bf[2 * p + 1][0], bf[2 * p + 1][1], addr);
        }
        uint32_t pa[2][4];
        #pragma unroll
        for (int mi = 0; mi < 2; mi++) {
            pa[mi][0] = packh2(sacc[mi][2 * jt][0], sacc[mi][2 * jt][1]);
            pa[mi][1] = packh2(sacc[mi][2 * jt][2], sacc[mi][2 * jt][3]);
            if (jt < 3) {
                pa[mi][2] = packh2(sacc[mi][2 * jt + 1][0], sacc[mi][2 * jt + 1][1]);
                pa[mi][3] = packh2(sacc[mi][2 * jt + 1][2], sacc[mi][2 * jt + 1][3]);
            } else {
                pa[mi][2] = 0u;
                pa[mi][3] = 0u;
            }
        }
        #pragma unroll
        for (int mi = 0; mi < 2; mi++)
            #pragma unroll
            for (int nd = 0; nd < 4; nd++)
                mma_f16(oacc[mi][nd], pa[mi], bf[nd]);
    }

    #pragma unroll
    for (int mi = 0; mi < 2; mi++) {
        int r0 = mwarp * 32 + mi * 16 + g;
        int r1 = r0 + 8;
        #pragma unroll
        for (int nd = 0; nd < 4; nd++) {
            int d0 = nd * 8 + 2 * t;
            if (r0 < NTOK)
                *(uint32_t*)(ctxh + ((size_t)w * NTOK + r0) * CDIM + h * HDIM + d0)
                    = packh2(oacc[mi][nd][0], oacc[mi][nd][1]);
            if (r1 < NTOK)
                *(uint32_t*)(ctxh + ((size_t)w * NTOK + r1) * CDIM + h * HDIM + d0)
                    = packh2(oacc[mi][nd][2], oacc[mi][nd][3]);
        }
    }
}

// ---------------------------------------------------------------------------
// Launch
// ---------------------------------------------------------------------------
extern "C" void kernel_launch(void* const* d_in, const int* in_sizes, int n_in,
                              void* d_out, int out_size)
{
    const float* x     = (const float*)d_in[0];
    const float* Wqkv  = (const float*)d_in[1];
    const float* bqkv  = (const float*)d_in[2];
    const float* Wproj = (const float*)d_in[3];
    const float* bproj = (const float*)d_in[4];
    const float* table = (const float*)d_in[5];
    const int*   relix = (const int*)d_in[6];
    float* out = (float*)d_out;

    __half *qkvh, *ctxh, *xh, *wqh, *wph;
    float* bias_g;
    cudaGetSymbolAddress((void**)&qkvh, g_qkvh);
    cudaGetSymbolAddress((void**)&ctxh, g_ctxh);
    cudaGetSymbolAddress((void**)&xh,   g_xh);
    cudaGetSymbolAddress((void**)&wqh,  g_wqh);
    cudaGetSymbolAddress((void**)&wph,  g_wph);
    cudaGetSymbolAddress((void**)&bias_g, g_bias);

    cudaFuncSetAttribute(gemm_f16_kernel,
                         cudaFuncAttributeMaxDynamicSharedMemorySize, GEMM_SMEM);

    // 0) prep
    f2h_kernel<<<4096, 256>>>((const float4*)x, (uint4*)xh, (MROWS * KDIM) / 8);
    transpose_h_kernel<<<dim3(N_QKV / 32, KDIM / 32), dim3(32, 8)>>>(
        Wqkv, wqh, KDIM, N_QKV);
    transpose_h_kernel<<<dim3(CDIM / 32, KDIM / 32), dim3(32, 8)>>>(
        Wproj, wph, KDIM, CDIM);
    bias_build_kernel<<<(HEADS * NTOK * NTOK + 255) / 256, 256>>>(
        table, relix, bias_g);

    // 1) qkv = half(x @ W_qkv + b)   (M=200704, N=1152, K=384)
    gemm_f16_kernel<<<dim3(N_QKV / 128, MROWS / 128), 256, GEMM_SMEM>>>(
        xh, wqh, bqkv, qkvh, N_QKV, 1);

    // 2) attention (fp16 tensor-core), one block per (window, head-pair)
    attn_h_kernel<<<dim3(BTOT, HEADS / 2), 128>>>(qkvh, bias_g, ctxh);

    // 3) out = ctx @ W_proj + b      (M=200704, N=384, K=384), f32 out
    gemm_f16_kernel<<<dim3(CDIM / 128, MROWS / 128), 256, GEMM_SMEM>>>(
        ctxh, wph, bproj, out, CDIM, 0);
}